// round 7
// baseline (speedup 1.0000x reference)
#include <cuda_runtime.h>
#include <cuda_bf16.h>
#include <cuda_fp16.h>
#include <cstdint>

#define NN    50000
#define NE    400000
#define INC   128
#define HID   256
#define ED    32

// ---------------- scratch (static device buffers; no allocation) ----------------
__device__ float g_Xs [NN * HID];
__device__ float g_Xd [NN * HID];
__device__ float g_h  [NN * HID];          // head temp (fp32)
__device__ __half g_Ea[NE * HID];          // per-edge We@attr + bias (fp16)
__device__ int   g_degi[NN];
__device__ int   g_rowstart[NN + 1];
__device__ int   g_cursor[NN];
__device__ int   g_csr_src[NE];
__device__ int   g_csr_eid[NE];

// bf16 split buffers
__device__ __nv_bfloat16 g_xh[NN * INC], g_xl[NN * INC];
__device__ __nv_bfloat16 g_eah[NE * ED], g_eal[NE * ED];
__device__ __nv_bfloat16 g_ch[NN * HID], g_cl[NN * HID];   // node feats ping
__device__ __nv_bfloat16 g_dh[NN * HID], g_dl[NN * HID];   // node feats pong
__device__ __nv_bfloat16 g_agh[NN * HID], g_agl[NN * HID]; // aggregate split

// weight split scratch
#define OF_E0 0
#define OF_N0 73728
#define OF_EW 172032
#define OF_NW 450560
#define OF_H1 712704
#define WTOT  778240
__device__ __nv_bfloat16 g_wh[WTOT], g_wl[WTOT];

// ---------------- utility kernels ----------------
__global__ void zero_kernel(float* p, int n4) {
    int i = blockIdx.x * blockDim.x + threadIdx.x;
    if (i < n4) reinterpret_cast<float4*>(p)[i] = make_float4(0.f, 0.f, 0.f, 0.f);
}

__global__ void hist_kernel(const int* __restrict__ dst, int* degi, int E) {
    int e = blockIdx.x * blockDim.x + threadIdx.x;
    if (e < E) atomicAdd(&degi[dst[e]], 1);
}

__global__ void scan_kernel(const int* __restrict__ deg,
                            int* __restrict__ rowstart,
                            int* __restrict__ cursor, int n)
{
    __shared__ int wsum[32];
    __shared__ int woff[32];
    __shared__ int carry_s;
    __shared__ int tot_s;
    const int tid = threadIdx.x, lane = tid & 31, wid = tid >> 5;
    if (tid == 0) carry_s = 0;
    __syncthreads();

    for (int base = 0; base < n; base += 1024) {
        int i = base + tid;
        int v = (i < n) ? deg[i] : 0;
        int incl = v;
#pragma unroll
        for (int off = 1; off < 32; off <<= 1) {
            int t = __shfl_up_sync(0xffffffffu, incl, off);
            if (lane >= off) incl += t;
        }
        if (lane == 31) wsum[wid] = incl;
        __syncthreads();
        if (wid == 0) {
            int s = wsum[lane];
            int si = s;
#pragma unroll
            for (int off = 1; off < 32; off <<= 1) {
                int t = __shfl_up_sync(0xffffffffu, si, off);
                if (lane >= off) si += t;
            }
            woff[lane] = si - s;
            if (lane == 31) tot_s = si;
        }
        __syncthreads();
        int excl_all = carry_s + woff[wid] + (incl - v);
        if (i < n) { rowstart[i] = excl_all; cursor[i] = excl_all; }
        __syncthreads();
        if (tid == 0) carry_s += tot_s;
        __syncthreads();
    }
    if (tid == 0) rowstart[n] = carry_s;
}

__global__ void scatter_kernel(const int* __restrict__ src, const int* __restrict__ dst,
                               int* __restrict__ cursor,
                               int* __restrict__ csr_src, int* __restrict__ csr_eid, int E)
{
    int e = blockIdx.x * blockDim.x + threadIdx.x;
    if (e < E) {
        int d = dst[e];
        int pos = atomicAdd(&cursor[d], 1);
        csr_src[pos] = src[e];
        csr_eid[pos] = e;
    }
}

// ---------------- fp32 -> bf16 hi/lo split (inputs + weights only) ----------------
__global__ void split_kernel(const float* __restrict__ src,
                             __nv_bfloat16* __restrict__ hi,
                             __nv_bfloat16* __restrict__ lo, int n4)
{
    int i = blockIdx.x * blockDim.x + threadIdx.x;
    if (i >= n4) return;
    float4 v = reinterpret_cast<const float4*>(src)[i];
    float vv[4] = {v.x, v.y, v.z, v.w};
    __nv_bfloat16 h[4], l[4];
#pragma unroll
    for (int j = 0; j < 4; j++) {
        h[j] = __float2bfloat16(vv[j]);
        l[j] = __float2bfloat16(vv[j] - __bfloat162float(h[j]));
    }
    reinterpret_cast<__nv_bfloat162*>(hi)[2 * i]     = __halves2bfloat162(h[0], h[1]);
    reinterpret_cast<__nv_bfloat162*>(hi)[2 * i + 1] = __halves2bfloat162(h[2], h[3]);
    reinterpret_cast<__nv_bfloat162*>(lo)[2 * i]     = __halves2bfloat162(l[0], l[1]);
    reinterpret_cast<__nv_bfloat162*>(lo)[2 * i + 1] = __halves2bfloat162(l[2], l[3]);
}

// ---------------- CSR mean aggregation (fp16 Ea in, bf16 hi/lo out) ----------------
#define AGG_CTAS 1184

__global__ __launch_bounds__(256) void agg2_kernel(
    const float* __restrict__ Xs, const float* __restrict__ Xd,
    const __half* __restrict__ Ea,
    const int* __restrict__ rowstart,
    const int* __restrict__ csr_src, const int* __restrict__ csr_eid,
    __nv_bfloat16* __restrict__ agh, __nv_bfloat16* __restrict__ agl)
{
    const int j = threadIdx.x;
    for (int d = blockIdx.x; d < NN; d += gridDim.x) {
        const int rs = __ldg(&rowstart[d]);
        const int re = __ldg(&rowstart[d + 1]);
        const float xd = Xd[(long)d * HID + j];
        float acc0 = 0.f, acc1 = 0.f;
        int p = rs;
        for (; p + 1 < re; p += 2) {
            const int s0 = __ldg(&csr_src[p]);
            const int e0 = __ldg(&csr_eid[p]);
            const int s1 = __ldg(&csr_src[p + 1]);
            const int e1 = __ldg(&csr_eid[p + 1]);
            const float m0 = __ldg(&Xs[(long)s0 * HID + j]) + __half2float(__ldg(&Ea[(long)e0 * HID + j])) + xd;
            const float m1 = __ldg(&Xs[(long)s1 * HID + j]) + __half2float(__ldg(&Ea[(long)e1 * HID + j])) + xd;
            acc0 += fmaxf(m0, 0.f);
            acc1 += fmaxf(m1, 0.f);
        }
        if (p < re) {
            const int s0 = __ldg(&csr_src[p]);
            const int e0 = __ldg(&csr_eid[p]);
            acc0 += fmaxf(__ldg(&Xs[(long)s0 * HID + j]) + __half2float(__ldg(&Ea[(long)e0 * HID + j])) + xd, 0.f);
        }
        const int  deg = re - rs;
        const float inv = 1.f / (float)((deg > 1) ? deg : 1);
        const float v = (acc0 + acc1) * inv;
        const __nv_bfloat16 hv = __float2bfloat16(v);
        agh[(long)d * HID + j] = hv;
        agl[(long)d * HID + j] = __float2bfloat16(v - __bfloat162float(hv));
    }
}

// ---------------- bf16 split tensor-core GEMM, 4-stage pipeline ----------------
struct Segs {
    const __nv_bfloat16* A[6];
    const __nv_bfloat16* W[6];
    int K[6];
    int n;
};

#define GBM 128
#define GBN 128
#define GBK 32
#define ASTR 40
#define BSTR 136
#define STAGES 4
#define A_ST_ELEM (GBM * ASTR)
#define B_ST_ELEM (GBK * BSTR)
#define SMEM_BYTES ((STAGES * (A_ST_ELEM + B_ST_ELEM)) * 2)

__device__ __forceinline__ void mma16816(float* c, const uint32_t* a, const uint32_t* b) {
    asm volatile(
        "mma.sync.aligned.m16n8k16.row.col.f32.bf16.bf16.f32 "
        "{%0,%1,%2,%3}, {%4,%5,%6,%7}, {%8,%9}, {%0,%1,%2,%3};"
        : "+f"(c[0]), "+f"(c[1]), "+f"(c[2]), "+f"(c[3])
        : "r"(a[0]), "r"(a[1]), "r"(a[2]), "r"(a[3]), "r"(b[0]), "r"(b[1]));
}

// out_mode: 0 = fp32 C, 1 = fp16 C, 2 = bf16 hi/lo (C=hi, C2=lo)
__global__ __launch_bounds__(256, 2) void bgemm_kernel(
    Segs S, const float* __restrict__ bias, int relu,
    void* __restrict__ Cv, void* __restrict__ C2v, int out_mode, int M, int N)
{
    extern __shared__ __nv_bfloat16 smem[];
    __nv_bfloat16* sA = smem;                       // STAGES * A_ST_ELEM
    __nv_bfloat16* sB = smem + STAGES * A_ST_ELEM;  // STAGES * B_ST_ELEM

    const int tid  = threadIdx.x;
    const int bm   = blockIdx.y * GBM;
    const int bn   = blockIdx.x * GBN;
    const int wid  = tid >> 5, lane = tid & 31;
    const int wm   = wid & 3, wn = wid >> 2;

    float acc[2][8][4];
#pragma unroll
    for (int i = 0; i < 2; i++)
#pragma unroll
        for (int j = 0; j < 8; j++)
#pragma unroll
            for (int q = 0; q < 4; q++) acc[i][j][q] = 0.f;

    int total = 0;
#pragma unroll
    for (int i = 0; i < 6; i++) if (i < S.n) total += S.K[i] / GBK;

    auto load_tile = [&](int seg, int k0, int st) {
        const __nv_bfloat16* A = S.A[seg];
        const __nv_bfloat16* W = S.W[seg];
        const int K = S.K[seg];
        __nv_bfloat16* dA = sA + st * A_ST_ELEM;
        __nv_bfloat16* dB = sB + st * B_ST_ELEM;
#pragma unroll
        for (int t = 0; t < 2; t++) {
            int c = tid + t * 256;
            int row = c >> 2, sg = c & 3;
            int r = bm + row;
            int valid = (r < M);
            const __nv_bfloat16* src = A + (long)(valid ? r : 0) * K + k0 + sg * 8;
            uint32_t dst = (uint32_t)__cvta_generic_to_shared(&dA[row * ASTR + sg * 8]);
            int sz = valid ? 16 : 0;
            asm volatile("cp.async.cg.shared.global [%0], [%1], 16, %2;\n"
                         :: "r"(dst), "l"(src), "r"(sz));
        }
#pragma unroll
        for (int t = 0; t < 2; t++) {
            int c = tid + t * 256;
            int row = c >> 4, sg = c & 15;
            const __nv_bfloat16* src = W + (long)(k0 + row) * N + bn + sg * 8;
            uint32_t dst = (uint32_t)__cvta_generic_to_shared(&dB[row * BSTR + sg * 8]);
            asm volatile("cp.async.cg.shared.global [%0], [%1], 16;\n"
                         :: "r"(dst), "l"(src));
        }
    };

    auto compute = [&](int st) {
        const __nv_bfloat16* cA = sA + st * A_ST_ELEM;
        const __nv_bfloat16* cB = sB + st * B_ST_ELEM;
#pragma unroll
        for (int kk = 0; kk < GBK; kk += 16) {
            uint32_t af[2][4];
#pragma unroll
            for (int mi = 0; mi < 2; mi++) {
                int row = wm * 32 + mi * 16 + (lane & 15);
                int col = kk + (lane >> 4) * 8;
                uint32_t addr = (uint32_t)__cvta_generic_to_shared(&cA[row * ASTR + col]);
                asm volatile("ldmatrix.sync.aligned.m8n8.x4.shared.b16 {%0,%1,%2,%3}, [%4];"
                             : "=r"(af[mi][0]), "=r"(af[mi][1]), "=r"(af[mi][2]), "=r"(af[mi][3])
                             : "r"(addr));
            }
            uint32_t bfr[4][4];
#pragma unroll
            for (int nj = 0; nj < 4; nj++) {
                int row = kk + (lane & 7) + ((lane >> 3) & 1) * 8;
                int col = wn * 64 + nj * 16 + (lane >> 4) * 8;
                uint32_t addr = (uint32_t)__cvta_generic_to_shared(&cB[row * BSTR + col]);
                asm volatile("ldmatrix.sync.aligned.m8n8.x4.trans.shared.b16 {%0,%1,%2,%3}, [%4];"
                             : "=r"(bfr[nj][0]), "=r"(bfr[nj][1]), "=r"(bfr[nj][2]), "=r"(bfr[nj][3])
                             : "r"(addr));
            }
#pragma unroll
            for (int mi = 0; mi < 2; mi++)
#pragma unroll
                for (int nj = 0; nj < 8; nj++) {
                    const uint32_t* b = (nj & 1) ? &bfr[nj >> 1][2] : &bfr[nj >> 1][0];
                    mma16816(acc[mi][nj], af[mi], b);
                }
        }
    };

    // (seg,k0) iterator state for the load stream
    int lseg = 0, lk0 = 0;
    auto advance = [&]() {
        lk0 += GBK;
        if (lk0 >= S.K[lseg]) { lseg++; lk0 = 0; }
    };

    // prologue: fill STAGES-1 stages
    for (int t = 0; t < STAGES - 1; ++t) {
        if (t < total) { load_tile(lseg, lk0, t); advance(); }
        asm volatile("cp.async.commit_group;\n");
    }

    for (int t = 0; t < total; ++t) {
        asm volatile("cp.async.wait_group %0;\n" :: "n"(STAGES - 2));
        __syncthreads();
        // issue load for stage t+STAGES-1 (overwrites stage (t-1)%STAGES, now free)
        if (t + STAGES - 1 < total) { load_tile(lseg, lk0, (t + STAGES - 1) % STAGES); advance(); }
        asm volatile("cp.async.commit_group;\n");
        compute(t % STAGES);
    }

    // epilogue
#pragma unroll
    for (int mi = 0; mi < 2; mi++) {
        int r0 = bm + wm * 32 + mi * 16 + (lane >> 2);
#pragma unroll
        for (int nj = 0; nj < 8; nj++) {
            int c = bn + wn * 64 + nj * 8 + (lane & 3) * 2;
            float b0 = 0.f, b1 = 0.f;
            if (bias) { b0 = bias[c]; b1 = bias[c + 1]; }
            float v[2][2] = {{acc[mi][nj][0] + b0, acc[mi][nj][1] + b1},
                             {acc[mi][nj][2] + b0, acc[mi][nj][3] + b1}};
            if (relu) {
#pragma unroll
                for (int q = 0; q < 2; q++) { v[q][0] = fmaxf(v[q][0], 0.f); v[q][1] = fmaxf(v[q][1], 0.f); }
            }
#pragma unroll
            for (int q = 0; q < 2; q++) {
                int r = r0 + q * 8;
                if (r >= M) continue;
                if (out_mode == 0) {
                    *reinterpret_cast<float2*>((float*)Cv + (long)r * N + c) = make_float2(v[q][0], v[q][1]);
                } else if (out_mode == 1) {
                    *reinterpret_cast<__half2*>((__half*)Cv + (long)r * N + c) =
                        __floats2half2_rn(v[q][0], v[q][1]);
                } else {
                    __nv_bfloat16 h0 = __float2bfloat16(v[q][0]);
                    __nv_bfloat16 h1 = __float2bfloat16(v[q][1]);
                    *reinterpret_cast<__nv_bfloat162*>((__nv_bfloat16*)Cv + (long)r * N + c) =
                        __halves2bfloat162(h0, h1);
                    __nv_bfloat16 l0 = __float2bfloat16(v[q][0] - __bfloat162float(h0));
                    __nv_bfloat16 l1 = __float2bfloat16(v[q][1] - __bfloat162float(h1));
                    *reinterpret_cast<__nv_bfloat162*>((__nv_bfloat16*)C2v + (long)r * N + c) =
                        __halves2bfloat162(l0, l1);
                }
            }
        }
    }
}

// ---------------- head: out[n] = dot(relu_feats[n], w2) + b2 ----------------
__global__ void head_out_kernel(const float* __restrict__ T,
                                const float* __restrict__ w2,
                                const float* __restrict__ b2,
                                float* __restrict__ out, int n)
{
    int gw   = (blockIdx.x * blockDim.x + threadIdx.x) >> 5;
    int lane = threadIdx.x & 31;
    if (gw >= n) return;
    const float* t = T + (long)gw * HID;
    float acc = 0.f;
#pragma unroll
    for (int k = lane; k < HID; k += 32) acc = fmaf(t[k], w2[k], acc);
#pragma unroll
    for (int o = 16; o; o >>= 1) acc += __shfl_xor_sync(0xffffffffu, acc, o);
    if (lane == 0) out[gw] = acc + b2[0];
}

// ---------------- host orchestration ----------------
template <typename T>
static T* sym_addr(const void* symbol) {
    void* p = nullptr;
    cudaGetSymbolAddress(&p, symbol);
    return (T*)p;
}

typedef const __nv_bfloat16* bfp;

static void seg3(Segs& S, bfp Ah, bfp Al, bfp Wh, bfp Wl, int K) {
    int i = S.n;
    S.A[i] = Ah; S.W[i] = Wh; S.K[i] = K; i++;
    S.A[i] = Ah; S.W[i] = Wl; S.K[i] = K; i++;
    S.A[i] = Al; S.W[i] = Wh; S.K[i] = K; i++;
    S.n = i;
}

static void run_bgemm(const Segs& S, const float* bias, int relu,
                      void* C, void* C2, int out_mode, int M, int N, cudaStream_t s)
{
    static bool attr_set = false;
    if (!attr_set) {
        cudaFuncSetAttribute(bgemm_kernel, cudaFuncAttributeMaxDynamicSharedMemorySize, SMEM_BYTES);
        attr_set = true;
    }
    dim3 grid(N / GBN, (M + GBM - 1) / GBM);
    bgemm_kernel<<<grid, 256, SMEM_BYTES, s>>>(S, bias, relu, C, C2, out_mode, M, N);
}

static void run_split(const float* src, __nv_bfloat16* hi, __nv_bfloat16* lo,
                      int n, cudaStream_t s)
{
    int n4 = n / 4;
    split_kernel<<<(n4 + 255) / 256, 256, 0, s>>>(src, hi, lo, n4);
}

extern "C" void kernel_launch(void* const* d_in, const int* in_sizes, int n_in,
                              void* d_out, int out_size)
{
    cudaStream_t s = 0;
    const float* x     = (const float*)d_in[0];
    const int*   eidx  = (const int*)  d_in[1];
    const float* eattr = (const float*)d_in[2];
    const float* e0_w  = (const float*)d_in[3];
    const float* e0_b  = (const float*)d_in[4];
    const float* n0_w  = (const float*)d_in[5];
    const float* n0_b  = (const float*)d_in[6];
    const float* e_w   = (const float*)d_in[7];
    const float* e_b   = (const float*)d_in[8];
    const float* n_w   = (const float*)d_in[9];
    const float* n_b   = (const float*)d_in[10];
    const float* h1_w  = (const float*)d_in[11];
    const float* h1_b  = (const float*)d_in[12];
    const float* h2_w  = (const float*)d_in[13];
    const float* h2_b  = (const float*)d_in[14];

    const int* src = eidx;
    const int* dst = eidx + NE;

    float*  Xs   = sym_addr<float>(g_Xs);
    float*  Xd   = sym_addr<float>(g_Xd);
    float*  htmp = sym_addr<float>(g_h);
    __half* Ea   = sym_addr<__half>(g_Ea);
    int*    degi = sym_addr<int>(g_degi);
    int*    rowS = sym_addr<int>(g_rowstart);
    int*    curS = sym_addr<int>(g_cursor);
    int*    csrS = sym_addr<int>(g_csr_src);
    int*    csrE = sym_addr<int>(g_csr_eid);

    __nv_bfloat16* xh  = sym_addr<__nv_bfloat16>(g_xh);
    __nv_bfloat16* xl  = sym_addr<__nv_bfloat16>(g_xl);
    __nv_bfloat16* eah = sym_addr<__nv_bfloat16>(g_eah);
    __nv_bfloat16* eal = sym_addr<__nv_bfloat16>(g_eal);
    __nv_bfloat16* ch  = sym_addr<__nv_bfloat16>(g_ch);
    __nv_bfloat16* cl  = sym_addr<__nv_bfloat16>(g_cl);
    __nv_bfloat16* dh  = sym_addr<__nv_bfloat16>(g_dh);
    __nv_bfloat16* dl  = sym_addr<__nv_bfloat16>(g_dl);
    __nv_bfloat16* agh = sym_addr<__nv_bfloat16>(g_agh);
    __nv_bfloat16* agl = sym_addr<__nv_bfloat16>(g_agl);
    __nv_bfloat16* wh  = sym_addr<__nv_bfloat16>(g_wh);
    __nv_bfloat16* wl  = sym_addr<__nv_bfloat16>(g_wl);

    // ---------- splits (weights + static inputs) ----------
    run_split(e0_w, wh + OF_E0, wl + OF_E0, 288 * 256, s);
    run_split(n0_w, wh + OF_N0, wl + OF_N0, 384 * 256, s);
    run_split(e_w,  wh + OF_EW, wl + OF_EW, 2 * 544 * 256, s);
    run_split(n_w,  wh + OF_NW, wl + OF_NW, 2 * 512 * 256, s);
    run_split(h1_w, wh + OF_H1, wl + OF_H1, 256 * 256, s);
    run_split(x,     xh,  xl,  NN * INC, s);
    run_split(eattr, eah, eal, NE * ED, s);

    // ---------- CSR build ----------
    zero_kernel<<<(NN / 4 + 255) / 256, 256, 0, s>>>((float*)degi, NN / 4);
    hist_kernel<<<(NE + 255) / 256, 256, 0, s>>>(dst, degi, NE);
    scan_kernel<<<1, 1024, 0, s>>>(degi, rowS, curS, NN);
    scatter_kernel<<<(NE + 255) / 256, 256, 0, s>>>(src, dst, curS, csrS, csrE, NE);

    // ---------- layer 0 (C = 128) ----------
    {
        bfp Wsh = wh + OF_E0,             Wsl = wl + OF_E0;
        bfp Wdh = wh + OF_E0 + 128 * 256, Wdl = wl + OF_E0 + 128 * 256;
        bfp Weh = wh + OF_E0 + 256 * 256, Wel = wl + OF_E0 + 256 * 256;

        Segs S1 = {}; seg3(S1, xh, xl, Wsh, Wsl, INC);
        run_bgemm(S1, nullptr, 0, Xs, nullptr, 0, NN, HID, s);
        Segs S2 = {}; seg3(S2, xh, xl, Wdh, Wdl, INC);
        run_bgemm(S2, nullptr, 0, Xd, nullptr, 0, NN, HID, s);
        Segs S3 = {}; seg3(S3, eah, eal, Weh, Wel, ED);
        run_bgemm(S3, e0_b, 0, Ea, nullptr, 1, NE, HID, s);

        agg2_kernel<<<AGG_CTAS, 256, 0, s>>>(Xs, Xd, Ea, rowS, csrS, csrE, agh, agl);

        Segs S4 = {};
        seg3(S4, xh, xl, wh + OF_N0, wl + OF_N0, INC);
        seg3(S4, agh, agl, wh + OF_N0 + 128 * 256, wl + OF_N0 + 128 * 256, HID);
        run_bgemm(S4, n0_b, 1, ch, cl, 2, NN, HID, s);
    }

    // ---------- layers 1..2 (C = 256) ----------
    __nv_bfloat16 *curh = ch, *curl = cl, *nxth = dh, *nxtl = dl;
    for (int L = 0; L < 2; ++L) {
        bfp ewh = wh + OF_EW + (long)L * 544 * 256;
        bfp ewl = wl + OF_EW + (long)L * 544 * 256;
        bfp nwh = wh + OF_NW + (long)L * 512 * 256;
        bfp nwl = wl + OF_NW + (long)L * 512 * 256;
        const float* eb = e_b + (long)L * HID;
        const float* nb = n_b + (long)L * HID;

        Segs S1 = {}; seg3(S1, curh, curl, ewh, ewl, HID);
        run_bgemm(S1, nullptr, 0, Xs, nullptr, 0, NN, HID, s);
        Segs S2 = {}; seg3(S2, curh, curl, ewh + 256 * 256, ewl + 256 * 256, HID);
        run_bgemm(S2, nullptr, 0, Xd, nullptr, 0, NN, HID, s);
        Segs S3 = {}; seg3(S3, eah, eal, ewh + 512 * 256, ewl + 512 * 256, ED);
        run_bgemm(S3, eb, 0, Ea, nullptr, 1, NE, HID, s);

        agg2_kernel<<<AGG_CTAS, 256, 0, s>>>(Xs, Xd, Ea, rowS, csrS, csrE, agh, agl);

        Segs S4 = {};
        seg3(S4, curh, curl, nwh, nwl, HID);
        seg3(S4, agh, agl, nwh + 256 * 256, nwl + 256 * 256, HID);
        run_bgemm(S4, nb, 1, nxth, nxtl, 2, NN, HID, s);

        __nv_bfloat16* t;
        t = curh; curh = nxth; nxth = t;
        t = curl; curl = nxtl; nxtl = t;
    }

    // ---------- head ----------
    Segs SH = {}; seg3(SH, curh, curl, wh + OF_H1, wl + OF_H1, HID);
    run_bgemm(SH, h1_b, 1, htmp, nullptr, 0, NN, HID, s);
    head_out_kernel<<<(NN * 32 + 255) / 256, 256, 0, s>>>(htmp, h2_w, h2_b, (float*)d_out, NN);
}